// round 6
// baseline (speedup 1.0000x reference)
#include <cuda_runtime.h>
#include <cstdint>

#define BB 32
#define NN 65536
#define MM 64
#define TPB 256
#define PRED_PER_BLK 512
#define BLOCKS_A (NN / PRED_PER_BLK)        // 128 blocks/img for k_pairwise
#define BLOCKS_PER_IMG (NN / TPB)           // 256 blocks/img for k_loss
#define EPSV 1e-6f

// Scratch (static __device__ globals: no runtime allocation)
__device__ unsigned long long g_gt_best[BB * MM];       // packed (iou_bits<<32)|(~pred_idx)
__device__ float2             g_pred_best[BB * NN];     // (best_iou, bestj bits)
__device__ float4             g_partials[BB * BLOCKS_PER_IMG];
__device__ float4             g_img[BB];                // per-image (cls, reg, npos, -)

// ---------------------------------------------------------------------------
__global__ void k_init() {
    int t = blockIdx.x * blockDim.x + threadIdx.x;
    if (t < BB * MM) g_gt_best[t] = 0ull;
}

// ---------------------------------------------------------------------------
// Kernel A: 2 preds per thread. Per-pred best-GT argmax in registers;
// per-GT best-pred argmax via one REDUX + two ballots per warp per GT
// (amortized over 64 preds/warp), block staging, atomicMax on packed u64.
__global__ void __launch_bounds__(TPB) k_pairwise(const float* __restrict__ pred,
                                                  const float* __restrict__ gt) {
    const int b     = blockIdx.x / BLOCKS_A;
    const int chunk = blockIdx.x % BLOCKS_A;
    const int base  = chunk * PRED_PER_BLK;
    const int i0    = base + threadIdx.x;                 // lower pred
    const int i1    = i0 + TPB;                           // upper pred

    __shared__ float4 sgt[MM];
    __shared__ float  sga[MM];
    __shared__ unsigned long long sred[MM][TPB / 32];     // per-warp winners

    if (threadIdx.x < MM) {
        float4 g4 = ((const float4*)gt)[(size_t)b * MM + threadIdx.x];
        sgt[threadIdx.x] = g4;
        sga[threadIdx.x] = (g4.z - g4.x) * (g4.w - g4.y);
    }
    __syncthreads();

    const float* p0 = pred + ((size_t)b * NN + i0) * 5;
    const float* p1 = pred + ((size_t)b * NN + i1) * 5;
    float acx = p0[0], acy = p0[1], aw = p0[2], ah = p0[3];
    float bcx = p1[0], bcy = p1[1], bw = p1[2], bh = p1[3];
    float ax1 = acx - 0.5f * aw, ay1 = acy - 0.5f * ah;
    float ax2 = acx + 0.5f * aw, ay2 = acy + 0.5f * ah;
    float bx1 = bcx - 0.5f * bw, by1 = bcy - 0.5f * bh;
    float bx2 = bcx + 0.5f * bw, by2 = bcy + 0.5f * bh;
    float area_a = (ax2 - ax1) * (ay2 - ay1);
    float area_b = (bx2 - bx1) * (by2 - by1);

    float bestva = -1.0f, bestvb = -1.0f;
    int   bestja = 0,     bestjb = 0;
    const int lane = threadIdx.x & 31;
    const int warp = threadIdx.x >> 5;
    const unsigned int wbase = (unsigned int)(base + warp * 32);

    #pragma unroll 8
    for (int j = 0; j < MM; j++) {
        float4 g  = sgt[j];
        float ga  = sga[j];

        // pred A
        float x1a = fmaxf(ax1, g.x), y1a = fmaxf(ay1, g.y);
        float x2a = fminf(ax2, g.z), y2a = fminf(ay2, g.w);
        float ia  = fmaxf(x2a - x1a, 0.0f) * fmaxf(y2a - y1a, 0.0f);
        float ua  = area_a + ga - ia;
        float ioua = __fdividef(ia, fmaxf(ua, EPSV));
        if (ioua > bestva) { bestva = ioua; bestja = j; }

        // pred B
        float x1b = fmaxf(bx1, g.x), y1b = fmaxf(by1, g.y);
        float x2b = fminf(bx2, g.z), y2b = fminf(by2, g.w);
        float ib_ = fmaxf(x2b - x1b, 0.0f) * fmaxf(y2b - y1b, 0.0f);
        float ub  = area_b + ga - ib_;
        float ioub = __fdividef(ib_, fmaxf(ub, EPSV));
        if (ioub > bestvb) { bestvb = ioub; bestjb = j; }

        // per-GT warp argmax over 64 preds (iou >= 0: float bits monotone)
        unsigned int ba = __float_as_uint(ioua);
        unsigned int bb = __float_as_uint(ioub);
        unsigned int mv = __reduce_max_sync(0xffffffffu, max(ba, bb));
        unsigned int m0 = __ballot_sync(0xffffffffu, ba == mv);
        unsigned int m1 = __ballot_sync(0xffffffffu, bb == mv);
        if (lane == 0) {
            // all i0 indices in this warp < all i1 indices -> check m0 first
            unsigned int li = m0 ? (wbase + (unsigned int)(__ffs(m0) - 1))
                                 : (wbase + (unsigned int)TPB + (unsigned int)(__ffs(m1) - 1));
            sred[j][warp] = ((unsigned long long)mv << 32) | (0xFFFFFFFFu - li);
        }
    }

    g_pred_best[(size_t)b * NN + i0] = make_float2(bestva, __int_as_float(bestja));
    g_pred_best[(size_t)b * NN + i1] = make_float2(bestvb, __int_as_float(bestjb));

    __syncthreads();
    if (threadIdx.x < MM) {
        unsigned long long m = sred[threadIdx.x][0];
        #pragma unroll
        for (int wgi = 1; wgi < TPB / 32; wgi++) {
            unsigned long long v = sred[threadIdx.x][wgi];
            if (v > m) m = v;
        }
        atomicMax(&g_gt_best[b * MM + threadIdx.x], m);
    }
}

// ---------------------------------------------------------------------------
__device__ __forceinline__ float warp_sum(float v) {
    #pragma unroll
    for (int o = 16; o > 0; o >>= 1) v += __shfl_down_sync(0xffffffffu, v, o);
    return v;
}

// Kernel B: pos/neg assignment, focal + GIoU, block partial sums.
__global__ void __launch_bounds__(TPB) k_loss(const float* __restrict__ pred,
                                              const float* __restrict__ gt) {
    const int b = blockIdx.x / BLOCKS_PER_IMG;
    const int i = (blockIdx.x % BLOCKS_PER_IMG) * TPB + threadIdx.x;

    __shared__ float4 sgt[MM];
    __shared__ unsigned int sscat[MM];
    __shared__ float4 sredu[TPB / 32];

    if (threadIdx.x < MM) {
        sgt[threadIdx.x] = ((const float4*)gt)[(size_t)b * MM + threadIdx.x];
        unsigned long long pk = g_gt_best[b * MM + threadIdx.x];
        float v = __uint_as_float((unsigned int)(pk >> 32));
        unsigned int idx = 0xFFFFFFFFu - (unsigned int)(pk & 0xFFFFFFFFull);
        sscat[threadIdx.x] = (v > 0.1f) ? idx : 0xFFFFFFFFu;
    }
    __syncthreads();

    const float* p = pred + ((size_t)b * NN + i) * 5;
    float cx = p[0], cy = p[1], w = p[2], h = p[3], obj = p[4];
    float px1 = cx - 0.5f * w, py1 = cy - 0.5f * h;
    float px2 = cx + 0.5f * w, py2 = cy + 0.5f * h;
    float area_p = (px2 - px1) * (py2 - py1);

    float2 pb2 = g_pred_best[(size_t)b * NN + i];
    float bestv = pb2.x;
    int   bestj = __float_as_int(pb2.y);

    bool scat = false;
    #pragma unroll 8
    for (int j = 0; j < MM; j++) scat |= (sscat[j] == (unsigned int)i);

    bool pos   = scat || (bestv > 0.5f);
    bool neg   = bestv < 0.4f;
    bool valid = pos || neg;

    // focal
    float l   = obj;
    float t   = pos ? 1.0f : 0.0f;
    float bce = fmaxf(l, 0.0f) - l * t + log1pf(expf(-fabsf(l)));
    float pr  = 1.0f / (1.0f + expf(-l));
    float p_t = pos ? pr : 1.0f - pr;
    float a_t = pos ? 0.25f : 0.75f;
    float om  = 1.0f - p_t;
    float fl  = a_t * om * om * bce;

    // giou vs matched gt
    float4 g = sgt[bestj];
    float x1 = fmaxf(px1, g.x), y1 = fmaxf(py1, g.y);
    float x2 = fminf(px2, g.z), y2 = fminf(py2, g.w);
    float inter = fmaxf(x2 - x1, 0.0f) * fmaxf(y2 - y1, 0.0f);
    float ag  = (g.z - g.x) * (g.w - g.y);
    float uni = area_p + ag - inter;
    float iou = __fdividef(inter, fmaxf(uni, EPSV));
    float ex1 = fminf(px1, g.x), ey1 = fminf(py1, g.y);
    float ex2 = fmaxf(px2, g.z), ey2 = fmaxf(py2, g.w);
    float enc = (ex2 - ex1) * (ey2 - ey1);
    float giou = iou - __fdividef(enc - uni, fmaxf(enc, EPSV));
    float gterm = 1.0f - giou;

    float s0 = valid ? fl : 0.0f;
    float s1 = valid ? 1.0f : 0.0f;
    float s2 = pos ? gterm : 0.0f;
    float s3 = pos ? 1.0f : 0.0f;

    s0 = warp_sum(s0); s1 = warp_sum(s1); s2 = warp_sum(s2); s3 = warp_sum(s3);
    int lane = threadIdx.x & 31, warp = threadIdx.x >> 5;
    if (lane == 0) sredu[warp] = make_float4(s0, s1, s2, s3);
    __syncthreads();
    if (threadIdx.x < (TPB / 32)) {
        float4 v = sredu[threadIdx.x];
        #pragma unroll
        for (int o = (TPB / 64); o > 0; o >>= 1) {
            v.x += __shfl_down_sync(0xffu, v.x, o);
            v.y += __shfl_down_sync(0xffu, v.y, o);
            v.z += __shfl_down_sync(0xffu, v.z, o);
            v.w += __shfl_down_sync(0xffu, v.w, o);
        }
        if (threadIdx.x == 0) g_partials[blockIdx.x] = v;
    }
}

// ---------------------------------------------------------------------------
// Per-image reduction: one block per image, 256 partials each.
__global__ void __launch_bounds__(TPB) k_reduce_img() {
    const int b = blockIdx.x;
    __shared__ float4 s[TPB / 32];

    float4 v = g_partials[b * BLOCKS_PER_IMG + threadIdx.x];
    v.x = warp_sum(v.x); v.y = warp_sum(v.y);
    v.z = warp_sum(v.z); v.w = warp_sum(v.w);
    int lane = threadIdx.x & 31, warp = threadIdx.x >> 5;
    if (lane == 0) s[warp] = v;
    __syncthreads();
    if (threadIdx.x == 0) {
        float fls = 0.f, vc = 0.f, gts = 0.f, pc = 0.f;
        #pragma unroll
        for (int k = 0; k < TPB / 32; k++) {
            fls += s[k].x; vc += s[k].y; gts += s[k].z; pc += s[k].w;
        }
        float cls = (vc > 0.0f) ? fls / fmaxf(vc, 1.0f) : 0.0f;
        float reg = (pc > 0.0f) ? gts / fmaxf(pc, 1.0f) : 0.0f;
        g_img[b] = make_float4(cls, reg, pc, 0.0f);
    }
}

// Final combine: one warp over 32 images.
__global__ void k_final2(float* __restrict__ out) {
    float4 v = g_img[threadIdx.x];
    float cls = warp_sum(v.x);
    float reg = warp_sum(v.y);
    float pc  = warp_sum(v.z);
    if (threadIdx.x == 0) {
        float num_pos = fmaxf(pc, 1.0f);
        out[0] = cls / (float)BB + 2.0f * (reg / num_pos * (float)BB);
    }
}

// ---------------------------------------------------------------------------
extern "C" void kernel_launch(void* const* d_in, const int* in_sizes, int n_in,
                              void* d_out, int out_size) {
    const float* pred = (const float*)d_in[0];
    const float* gt   = (const float*)d_in[1];
    if (n_in >= 2 && in_sizes[0] == BB * MM * 4 && in_sizes[1] == BB * NN * 5) {
        pred = (const float*)d_in[1];
        gt   = (const float*)d_in[0];
    }
    float* out = (float*)d_out;

    k_init<<<(BB * MM + 255) / 256, 256>>>();
    k_pairwise<<<BB * BLOCKS_A, TPB>>>(pred, gt);
    k_loss<<<BB * BLOCKS_PER_IMG, TPB>>>(pred, gt);
    k_reduce_img<<<BB, TPB>>>();
    k_final2<<<1, 32>>>(out);
}